// round 3
// baseline (speedup 1.0000x reference)
#include <cuda_runtime.h>

// MoE conditional FFN: T=16 tokens, TOP_K=2, E=8 experts, H=1024, I=2816, fp32.
// Expert-major grouping: each used expert's weights stream from HBM exactly once
// (re-reads across that expert's pairs hit L1).
// Phase 1: h[pair, o] = silu(gate[e,o,:]·x[t]) * (down[e,o,:]·x[t])
// Phase 2: out[pair, hh] = up[e, hh, :] · h[pair, :]
//
// R2 changes vs R1: 1 row per warp (8x more blocks), no register preload of
// weight rows (L1 covers pair re-reads), dual accumulators to break FMA chains.
// Goal: occupancy 20% -> 50%+, phase2 DRAM 32% -> 60%+.

#define NTOK   16
#define TOPK   2
#define NPAIR  (NTOK * TOPK)       // 32
#define HID    1024
#define INTER  2816
#define NEXP   8

// Intermediate activations (32 * 2816 floats = 360 KB). Static device scratch.
__device__ float g_h[NPAIR * INTER];

// ---------------------------------------------------------------------------
// Phase 1: gate & down GEMVs + SiLU-mul.
// grid = (INTER/8, NEXP) = (352, 8), block = 256 (8 warps). Warp = one row.
// ---------------------------------------------------------------------------
__global__ __launch_bounds__(256)
void moe_phase1(const float* __restrict__ x,        // [T, H]
                const int*   __restrict__ eidx,     // [T, TOPK]
                const float* __restrict__ gate,     // [E, I, H]
                const float* __restrict__ down)     // [E, I, H]
{
    const int e = blockIdx.y;

    __shared__ int s_cnt;
    __shared__ int s_pair[NPAIR];
    if (threadIdx.x == 0) {
        int c = 0;
        #pragma unroll
        for (int i = 0; i < NPAIR; i++)
            if (eidx[i] == e) s_pair[c++] = i;
        s_cnt = c;
    }
    __syncthreads();
    const int cnt = s_cnt;
    if (cnt == 0) return;

    const int warp = threadIdx.x >> 5;
    const int lane = threadIdx.x & 31;
    const int row  = blockIdx.x * 8 + warp;          // < INTER always

    const float4* gr = reinterpret_cast<const float4*>(gate + (size_t)e * INTER * HID)
                       + (size_t)row * (HID / 4);
    const float4* dr = reinterpret_cast<const float4*>(down + (size_t)e * INTER * HID)
                       + (size_t)row * (HID / 4);

    for (int p = 0; p < cnt; p++) {
        const int pa = s_pair[p];
        const int t  = pa >> 1;
        const float4* xr = reinterpret_cast<const float4*>(x + (size_t)t * HID);

        float ag0 = 0.f, ag1 = 0.f, ad0 = 0.f, ad1 = 0.f;
        #pragma unroll
        for (int j = 0; j < 8; j += 2) {
            const float4 xa = xr[lane + 32 * j];
            const float4 ga = gr[lane + 32 * j];
            const float4 da = dr[lane + 32 * j];
            const float4 xb = xr[lane + 32 * (j + 1)];
            const float4 gb = gr[lane + 32 * (j + 1)];
            const float4 db = dr[lane + 32 * (j + 1)];
            ag0 = fmaf(ga.x, xa.x, ag0); ag0 = fmaf(ga.y, xa.y, ag0);
            ag0 = fmaf(ga.z, xa.z, ag0); ag0 = fmaf(ga.w, xa.w, ag0);
            ad0 = fmaf(da.x, xa.x, ad0); ad0 = fmaf(da.y, xa.y, ad0);
            ad0 = fmaf(da.z, xa.z, ad0); ad0 = fmaf(da.w, xa.w, ad0);
            ag1 = fmaf(gb.x, xb.x, ag1); ag1 = fmaf(gb.y, xb.y, ag1);
            ag1 = fmaf(gb.z, xb.z, ag1); ag1 = fmaf(gb.w, xb.w, ag1);
            ad1 = fmaf(db.x, xb.x, ad1); ad1 = fmaf(db.y, xb.y, ad1);
            ad1 = fmaf(db.z, xb.z, ad1); ad1 = fmaf(db.w, xb.w, ad1);
        }
        float ag = ag0 + ag1;
        float ad = ad0 + ad1;
        #pragma unroll
        for (int off = 16; off; off >>= 1) {
            ag += __shfl_xor_sync(0xFFFFFFFFu, ag, off);
            ad += __shfl_xor_sync(0xFFFFFFFFu, ad, off);
        }
        if (lane == 0) {
            const float s = ag / (1.f + __expf(-ag));   // silu(gate)
            g_h[(size_t)pa * INTER + row] = s * ad;
        }
    }
}

// ---------------------------------------------------------------------------
// Phase 2: out[pair, hh] = up[e, hh, :] . h[pair, :]
// grid = (HID/8, NEXP) = (128, 8), block = 256 (8 warps). Warp = one row.
// ---------------------------------------------------------------------------
__global__ __launch_bounds__(256)
void moe_phase2(const int*   __restrict__ eidx,     // [T, TOPK]
                const float* __restrict__ up,       // [E, H, I]
                float*       __restrict__ out)      // [T, TOPK, H]
{
    const int e = blockIdx.y;

    __shared__ int s_cnt;
    __shared__ int s_pair[NPAIR];
    if (threadIdx.x == 0) {
        int c = 0;
        #pragma unroll
        for (int i = 0; i < NPAIR; i++)
            if (eidx[i] == e) s_pair[c++] = i;
        s_cnt = c;
    }
    __syncthreads();
    const int cnt = s_cnt;
    if (cnt == 0) return;

    const int warp = threadIdx.x >> 5;
    const int lane = threadIdx.x & 31;
    const int hh   = blockIdx.x * 8 + warp;          // < HID always

    const float4* ur = reinterpret_cast<const float4*>(up + (size_t)e * HID * INTER)
                       + (size_t)hh * (INTER / 4);   // 704 float4 per row

    for (int p = 0; p < cnt; p++) {
        const int pa = s_pair[p];
        const float4* hr = reinterpret_cast<const float4*>(g_h + (size_t)pa * INTER);

        float a0 = 0.f, a1 = 0.f;
        #pragma unroll
        for (int j = 0; j < 22; j += 2) {
            const float4 ua = ur[lane + 32 * j];
            const float4 ha = hr[lane + 32 * j];
            const float4 ub = ur[lane + 32 * (j + 1)];
            const float4 hb = hr[lane + 32 * (j + 1)];
            a0 = fmaf(ua.x, ha.x, a0); a0 = fmaf(ua.y, ha.y, a0);
            a0 = fmaf(ua.z, ha.z, a0); a0 = fmaf(ua.w, ha.w, a0);
            a1 = fmaf(ub.x, hb.x, a1); a1 = fmaf(ub.y, hb.y, a1);
            a1 = fmaf(ub.z, hb.z, a1); a1 = fmaf(ub.w, hb.w, a1);
        }
        float acc = a0 + a1;
        #pragma unroll
        for (int off = 16; off; off >>= 1)
            acc += __shfl_xor_sync(0xFFFFFFFFu, acc, off);
        if (lane == 0)
            out[(size_t)pa * HID + hh] = acc;
    }
}

// ---------------------------------------------------------------------------
// Launch. Inputs (metadata order): x, expert_indices, gate_proj, up_proj, down_proj.
// Output: float32 [T, TOPK, H].
// ---------------------------------------------------------------------------
extern "C" void kernel_launch(void* const* d_in, const int* in_sizes, int n_in,
                              void* d_out, int out_size)
{
    const float* x    = (const float*)d_in[0];
    const int*   eidx = (const int*)  d_in[1];
    const float* gate = (const float*)d_in[2];
    const float* up   = (const float*)d_in[3];
    const float* down = (const float*)d_in[4];
    float* out = (float*)d_out;

    dim3 g1(INTER / 8, NEXP);    // 352 x 8 = 2816 blocks
    moe_phase1<<<g1, 256>>>(x, eidx, gate, down);

    dim3 g2(HID / 8, NEXP);      // 128 x 8 = 1024 blocks
    moe_phase2<<<g2, 256>>>(eidx, up, out);
}

// round 4
// speedup vs baseline: 1.0327x; 1.0327x over previous
#include <cuda_runtime.h>

// MoE conditional FFN: T=16, TOP_K=2, E=8, H=1024, I=2816, fp32.
// Expert-major grouping; R3: 4-pair chunked accumulation so each weight float4
// is loaded ONCE per chunk (4x less L1 traffic + 4 independent FMA chains),
// __launch_bounds__(256,4) to cap regs at 64 and get 32 warps/SM.

#define NTOK   16
#define TOPK   2
#define NPAIR  (NTOK * TOPK)       // 32
#define HID    1024
#define INTER  2816
#define NEXP   8

__device__ float g_h[NPAIR * INTER];   // 360 KB scratch

__device__ __forceinline__ float dot4(float4 a, float4 b, float acc) {
    acc = fmaf(a.x, b.x, acc);
    acc = fmaf(a.y, b.y, acc);
    acc = fmaf(a.z, b.z, acc);
    return fmaf(a.w, b.w, acc);
}

// ---------------------------------------------------------------------------
// Phase 1: h[pair,row] = silu(gate[e,row,:]·x[t]) * (down[e,row,:]·x[t])
// grid = (INTER/8, NEXP), block = 256. Warp = one row; pairs in chunks of 4.
// ---------------------------------------------------------------------------
__global__ __launch_bounds__(256, 4)
void moe_phase1(const float* __restrict__ x,        // [T, H]
                const int*   __restrict__ eidx,     // [T, TOPK]
                const float* __restrict__ gate,     // [E, I, H]
                const float* __restrict__ down)     // [E, I, H]
{
    const int e = blockIdx.y;

    __shared__ int s_cnt4;
    __shared__ int s_pair[NPAIR + 3];
    if (threadIdx.x == 0) {
        int c = 0;
        #pragma unroll
        for (int i = 0; i < NPAIR; i++)
            if (eidx[i] == e) s_pair[c++] = i;
        int c4 = (c + 3) & ~3;                 // pad to multiple of 4
        for (int i = c; i < c4; i++) s_pair[i] = s_pair[0];
        s_cnt4 = (c == 0) ? 0 : c4;
    }
    __syncthreads();
    const int cnt4 = s_cnt4;
    if (cnt4 == 0) return;

    const int warp = threadIdx.x >> 5;
    const int lane = threadIdx.x & 31;
    const int row  = blockIdx.x * 8 + warp;

    const float4* gr = reinterpret_cast<const float4*>(gate + (size_t)e * INTER * HID)
                       + (size_t)row * (HID / 4);
    const float4* dr = reinterpret_cast<const float4*>(down + (size_t)e * INTER * HID)
                       + (size_t)row * (HID / 4);

    for (int pb = 0; pb < cnt4; pb += 4) {
        const int pa0 = s_pair[pb + 0], pa1 = s_pair[pb + 1];
        const int pa2 = s_pair[pb + 2], pa3 = s_pair[pb + 3];
        const float4* x0 = reinterpret_cast<const float4*>(x + (size_t)(pa0 >> 1) * HID);
        const float4* x1 = reinterpret_cast<const float4*>(x + (size_t)(pa1 >> 1) * HID);
        const float4* x2 = reinterpret_cast<const float4*>(x + (size_t)(pa2 >> 1) * HID);
        const float4* x3 = reinterpret_cast<const float4*>(x + (size_t)(pa3 >> 1) * HID);

        float g0 = 0.f, g1 = 0.f, g2 = 0.f, g3 = 0.f;
        float d0 = 0.f, d1 = 0.f, d2 = 0.f, d3 = 0.f;

        #pragma unroll 2
        for (int j = 0; j < 8; j++) {
            const int k = lane + 32 * j;
            const float4 gw = gr[k];           // weight loaded ONCE for 4 pairs
            const float4 dw = dr[k];
            const float4 xa = x0[k];
            const float4 xb = x1[k];
            const float4 xc = x2[k];
            const float4 xd = x3[k];
            g0 = dot4(gw, xa, g0);  d0 = dot4(dw, xa, d0);
            g1 = dot4(gw, xb, g1);  d1 = dot4(dw, xb, d1);
            g2 = dot4(gw, xc, g2);  d2 = dot4(dw, xc, d2);
            g3 = dot4(gw, xd, g3);  d3 = dot4(dw, xd, d3);
        }

        #pragma unroll
        for (int off = 16; off; off >>= 1) {
            g0 += __shfl_xor_sync(0xFFFFFFFFu, g0, off);
            d0 += __shfl_xor_sync(0xFFFFFFFFu, d0, off);
            g1 += __shfl_xor_sync(0xFFFFFFFFu, g1, off);
            d1 += __shfl_xor_sync(0xFFFFFFFFu, d1, off);
            g2 += __shfl_xor_sync(0xFFFFFFFFu, g2, off);
            d2 += __shfl_xor_sync(0xFFFFFFFFu, d2, off);
            g3 += __shfl_xor_sync(0xFFFFFFFFu, g3, off);
            d3 += __shfl_xor_sync(0xFFFFFFFFu, d3, off);
        }
        if (lane == 0) {
            g_h[(size_t)pa0 * INTER + row] = (g0 / (1.f + __expf(-g0))) * d0;
            g_h[(size_t)pa1 * INTER + row] = (g1 / (1.f + __expf(-g1))) * d1;
            g_h[(size_t)pa2 * INTER + row] = (g2 / (1.f + __expf(-g2))) * d2;
            g_h[(size_t)pa3 * INTER + row] = (g3 / (1.f + __expf(-g3))) * d3;
        }
    }
}

// ---------------------------------------------------------------------------
// Phase 2: out[pair,hh] = up[e,hh,:] · h[pair,:]
// grid = (HID/8, NEXP), block = 256. Warp = one row; pairs in chunks of 4.
// ---------------------------------------------------------------------------
__global__ __launch_bounds__(256, 4)
void moe_phase2(const int*   __restrict__ eidx,     // [T, TOPK]
                const float* __restrict__ up,       // [E, H, I]
                float*       __restrict__ out)      // [T, TOPK, H]
{
    const int e = blockIdx.y;

    __shared__ int s_cnt4;
    __shared__ int s_pair[NPAIR + 3];
    if (threadIdx.x == 0) {
        int c = 0;
        #pragma unroll
        for (int i = 0; i < NPAIR; i++)
            if (eidx[i] == e) s_pair[c++] = i;
        int c4 = (c + 3) & ~3;
        for (int i = c; i < c4; i++) s_pair[i] = s_pair[0];
        s_cnt4 = (c == 0) ? 0 : c4;
    }
    __syncthreads();
    const int cnt4 = s_cnt4;
    if (cnt4 == 0) return;

    const int warp = threadIdx.x >> 5;
    const int lane = threadIdx.x & 31;
    const int hh   = blockIdx.x * 8 + warp;

    const float4* ur = reinterpret_cast<const float4*>(up + (size_t)e * HID * INTER)
                       + (size_t)hh * (INTER / 4);  // 704 float4 per row

    for (int pb = 0; pb < cnt4; pb += 4) {
        const int pa0 = s_pair[pb + 0], pa1 = s_pair[pb + 1];
        const int pa2 = s_pair[pb + 2], pa3 = s_pair[pb + 3];
        const float4* h0 = reinterpret_cast<const float4*>(g_h + (size_t)pa0 * INTER);
        const float4* h1 = reinterpret_cast<const float4*>(g_h + (size_t)pa1 * INTER);
        const float4* h2 = reinterpret_cast<const float4*>(g_h + (size_t)pa2 * INTER);
        const float4* h3 = reinterpret_cast<const float4*>(g_h + (size_t)pa3 * INTER);

        float a0 = 0.f, a1 = 0.f, a2 = 0.f, a3 = 0.f;

        #pragma unroll 2
        for (int j = 0; j < 22; j++) {
            const int k = lane + 32 * j;
            const float4 uw = ur[k];           // weight loaded ONCE for 4 pairs
            a0 = dot4(uw, h0[k], a0);
            a1 = dot4(uw, h1[k], a1);
            a2 = dot4(uw, h2[k], a2);
            a3 = dot4(uw, h3[k], a3);
        }

        #pragma unroll
        for (int off = 16; off; off >>= 1) {
            a0 += __shfl_xor_sync(0xFFFFFFFFu, a0, off);
            a1 += __shfl_xor_sync(0xFFFFFFFFu, a1, off);
            a2 += __shfl_xor_sync(0xFFFFFFFFu, a2, off);
            a3 += __shfl_xor_sync(0xFFFFFFFFu, a3, off);
        }
        if (lane == 0) {
            out[(size_t)pa0 * HID + hh] = a0;
            out[(size_t)pa1 * HID + hh] = a1;
            out[(size_t)pa2 * HID + hh] = a2;
            out[(size_t)pa3 * HID + hh] = a3;
        }
    }
}

// ---------------------------------------------------------------------------
extern "C" void kernel_launch(void* const* d_in, const int* in_sizes, int n_in,
                              void* d_out, int out_size)
{
    const float* x    = (const float*)d_in[0];
    const int*   eidx = (const int*)  d_in[1];
    const float* gate = (const float*)d_in[2];
    const float* up   = (const float*)d_in[3];
    const float* down = (const float*)d_in[4];
    float* out = (float*)d_out;

    dim3 g1(INTER / 8, NEXP);    // 352 x 8
    moe_phase1<<<g1, 256>>>(x, eidx, gate, down);

    dim3 g2(HID / 8, NEXP);      // 128 x 8
    moe_phase2<<<g2, 256>>>(eidx, up, out);
}